// round 2
// baseline (speedup 1.0000x reference)
#include <cuda_runtime.h>
#include <math.h>

// NCA update kernel, fp32 baseline.
// out = x + floor(rand+0.5) * (W2 @ relu(W1 @ perception(x) + b1))
// Shapes: x[32,12,256,256], w1[96,48], b1[96], w2[12,96], rand[32,1,256,256].

#define CC   12
#define FCH  96
#define K4C  48
#define HH   256
#define WW   256
#define TPX  128    // pixels (columns) per CTA
#define NT   256    // threads per CTA
#define FST  132    // padded row stride (floats) for F/H buffer

// dynamic smem layout (float offsets)
#define OFF_XS   0                         // [12][3][132] halo (cols 0..129 used)
#define SZ_XS    (CC*3*FST)                // 4752
#define OFF_FH   (OFF_XS + SZ_XS)          // [96][132]: F rows 0..47 then H rows 0..95
#define SZ_FH    (FCH*FST)                 // 12672
#define OFF_W1T  (OFF_FH + SZ_FH)          // [48][96]  w1T[k][o] = w1[o][k]
#define SZ_W1T   (K4C*FCH)                 // 4608
#define OFF_W2T  (OFF_W1T + SZ_W1T)        // [96][12]  w2T[k][o] = w2[o][k]
#define SZ_W2T   (FCH*CC)                  // 1152
#define OFF_B1   (OFF_W2T + SZ_W2T)        // [96]
#define SZ_B1    FCH
#define SMEM_FLOATS (OFF_B1 + SZ_B1)       // 23280
#define SMEM_BYTES  (SMEM_FLOATS * 4)      // 93120

__global__ __launch_bounds__(NT, 2)
void nca_kernel(const float* __restrict__ x,
                const float* __restrict__ w1,
                const float* __restrict__ b1,
                const float* __restrict__ w2,
                const float* __restrict__ rmask,
                float* __restrict__ out)
{
    extern __shared__ float sm[];
    float* XS  = sm + OFF_XS;
    float* FH  = sm + OFF_FH;
    float* W1T = sm + OFF_W1T;
    float* W2T = sm + OFF_W2T;
    float* B1  = sm + OFF_B1;

    const int tid = threadIdx.x;
    const int x0  = blockIdx.x * TPX;   // 0 or 128
    const int yy  = blockIdx.y;         // row 0..255
    const int bb  = blockIdx.z;         // batch 0..31

    // ---- Phase 0: stage weights (transposed) + biases ----
    for (int i = tid; i < FCH * K4C; i += NT) {
        int o = i / K4C, c = i % K4C;          // w1 row-major [96][48]
        W1T[c * FCH + o] = w1[i];
    }
    for (int i = tid; i < CC * FCH; i += NT) {
        int o = i / FCH, k = i % FCH;          // w2 row-major [12][96]
        W2T[k * CC + o] = w2[i];
    }
    if (tid < FCH) B1[tid] = b1[tid];

    // ---- stage halo: 12 channels x 3 rows x 130 cols (circular pad) ----
    const float* xb = x + (size_t)bb * CC * HH * WW;
    for (int i = tid; i < CC * 3 * 130; i += NT) {
        int c   = i / (3 * 130);
        int rem = i % (3 * 130);
        int r   = rem / 130;
        int col = rem % 130;
        int gy = yy + r - 1; if (gy < 0) gy += HH; if (gy >= HH) gy -= HH;
        int gx = x0 + col - 1; if (gx < 0) gx += WW; if (gx >= WW) gx -= WW;
        XS[(c * 3 + r) * FST + col] = xb[(c * HH + gy) * WW + gx];
    }
    __syncthreads();

    // ---- Phase 1: perception -> F[48][128] ----
    {
        int p   = tid & 127;
        int ch0 = (tid >> 7) * 6;   // thread group 0 -> ch 0..5, group 1 -> ch 6..11
        #pragma unroll
        for (int ci = 0; ci < 6; ci++) {
            int c = ch0 + ci;
            const float* r0 = &XS[(c * 3 + 0) * FST + p];
            const float* r1 = &XS[(c * 3 + 1) * FST + p];
            const float* r2 = &XS[(c * 3 + 2) * FST + p];
            float a00 = r0[0], a01 = r0[1], a02 = r0[2];
            float a10 = r1[0], a11 = r1[1], a12 = r1[2];
            float a20 = r2[0], a21 = r2[1], a22 = r2[2];
            float sx  = (a02 - a00) + 2.f * (a12 - a10) + (a22 - a20);
            float top = a00 + 2.f * a01 + a02;
            float bot = a20 + 2.f * a21 + a22;
            float sy  = bot - top;
            float lap = top + bot + 2.f * (a10 + a12) - 12.f * a11;
            int f0 = (c * 4) * FST + p;
            FH[f0        ] = a11;
            FH[f0 + FST  ] = sx;
            FH[f0 + 2*FST] = sy;
            FH[f0 + 3*FST] = lap;
        }
    }
    __syncthreads();

    // ---- Phase 2: GEMM1  H[96][128] = relu(W1 @ F + b1) ----
    // warp w handles pixels [w*16, w*16+16); lane: lh = hidden group of 12, lp = pixel group of 4
    const int wrp  = tid >> 5;
    const int ln   = tid & 31;
    const int lh   = ln & 7;
    const int lp   = ln >> 3;
    const int prow = lh * 12;              // hidden rows prow..prow+11
    const int pcol = wrp * 16 + lp * 4;    // pixels pcol..pcol+3

    float acc[12][4];
    #pragma unroll
    for (int i = 0; i < 12; i++) {
        float b = B1[prow + i];
        acc[i][0] = b; acc[i][1] = b; acc[i][2] = b; acc[i][3] = b;
    }

    #pragma unroll 4
    for (int k = 0; k < K4C; k++) {
        float4 fv = *(const float4*)(FH  + k * FST + pcol);
        float4 wA = *(const float4*)(W1T + k * FCH + prow);
        float4 wB = *(const float4*)(W1T + k * FCH + prow + 4);
        float4 wC = *(const float4*)(W1T + k * FCH + prow + 8);
        float wv[12];
        wv[0]=wA.x; wv[1]=wA.y; wv[2]=wA.z;  wv[3]=wA.w;
        wv[4]=wB.x; wv[5]=wB.y; wv[6]=wB.z;  wv[7]=wB.w;
        wv[8]=wC.x; wv[9]=wC.y; wv[10]=wC.z; wv[11]=wC.w;
        #pragma unroll
        for (int i = 0; i < 12; i++) {
            acc[i][0] = fmaf(wv[i], fv.x, acc[i][0]);
            acc[i][1] = fmaf(wv[i], fv.y, acc[i][1]);
            acc[i][2] = fmaf(wv[i], fv.z, acc[i][2]);
            acc[i][3] = fmaf(wv[i], fv.w, acc[i][3]);
        }
    }
    __syncthreads();   // all F reads complete before H overwrites the buffer

    #pragma unroll
    for (int i = 0; i < 12; i++) {
        float4 v;
        v.x = fmaxf(acc[i][0], 0.f);
        v.y = fmaxf(acc[i][1], 0.f);
        v.z = fmaxf(acc[i][2], 0.f);
        v.w = fmaxf(acc[i][3], 0.f);
        *(float4*)(FH + (prow + i) * FST + pcol) = v;
    }
    __syncthreads();

    // ---- Phase 3: GEMM2 out[12][128] = W2 @ H, masked residual epilogue ----
    {
        int p   = tid & 127;
        int oc0 = (tid >> 7) * 6;   // 0 or 6
        float o6[6] = {0.f, 0.f, 0.f, 0.f, 0.f, 0.f};
        #pragma unroll 4
        for (int k = 0; k < FCH; k++) {
            float h = FH[k * FST + p];
            // k*12 + oc0 (oc0 in {0,6}) is 8B-aligned -> 3x float2
            const float2* wr = (const float2*)(W2T + k * CC + oc0);
            float2 wa = wr[0], wb = wr[1], wc = wr[2];
            o6[0] = fmaf(wa.x, h, o6[0]);
            o6[1] = fmaf(wa.y, h, o6[1]);
            o6[2] = fmaf(wb.x, h, o6[2]);
            o6[3] = fmaf(wb.y, h, o6[3]);
            o6[4] = fmaf(wc.x, h, o6[4]);
            o6[5] = fmaf(wc.y, h, o6[5]);
        }
        float rm = rmask[((size_t)bb * HH + yy) * WW + x0 + p];
        float m  = floorf(rm + 0.5f);   // exact reference semantics
        #pragma unroll
        for (int i = 0; i < 6; i++) {
            int c = oc0 + i;
            float xc = XS[(c * 3 + 1) * FST + (p + 1)];
            out[(((size_t)bb * CC + c) * HH + yy) * WW + x0 + p] = fmaf(o6[i], m, xc);
        }
    }
}

extern "C" void kernel_launch(void* const* d_in, const int* in_sizes, int n_in,
                              void* d_out, int out_size)
{
    const float* x  = (const float*)d_in[0];
    const float* w1 = (const float*)d_in[1];
    const float* b1 = (const float*)d_in[2];
    const float* w2 = (const float*)d_in[3];
    const float* rm = (const float*)d_in[4];
    float* out = (float*)d_out;

    cudaFuncSetAttribute(nca_kernel, cudaFuncAttributeMaxDynamicSharedMemorySize, SMEM_BYTES);

    dim3 grid(WW / TPX, HH, 32);   // (2, 256, 32)
    nca_kernel<<<grid, NT, SMEM_BYTES>>>(x, w1, b1, w2, rm, out);
}